// round 7
// baseline (speedup 1.0000x reference)
#include <cuda_runtime.h>

typedef unsigned long long u64;
#define FULLMASK 0xffffffffu

constexpr int NWARPS   = 16;
constexpr int NTHREADS = NWARPS * 32;     // 512
constexpr int NGROUPS  = 24576 / 8;       // 3072 groups of 8 rows

// ---- shared memory layout (float offsets) ----
constexpr int OFF_W1  = 0;          // [64][256]
constexpr int OFF_W2P = 16384;      // float2[256][32]: (W2[j][L], W2[j][L+32])
constexpr int OFF_B1  = 32768;      // [256]
constexpr int OFF_WE  = 33024;      // [2][64]
constexpr int OFF_BE  = 33152;      // [64]
constexpr int OFF_M   = 33216;      // [4][9] bilinear energy coeffs (x 0.125*log2e), pad 40
constexpr int OFF_A0  = 33256;      // [4][64]  WeV0 @ Wo per head
constexpr int OFF_A1  = 33512;      // [4][64]
constexpr int OFF_K   = 33768;      // [64]     beV @ Wo + bo
constexpr int OFF_DUP = 33832;      // 10 x 64: g1lo,g1hi,lb1lo,lb1hi,b2lo,b2hi,g2lo,g2hi,lb2lo,lb2hi
constexpr int OFF_SCR = 34472;      // per-warp scratch: x pairs [0,512) + h half-chunk [512,1024); pkb aliases [0,528)
constexpr int SCR_FLOATS = 1024;
constexpr int SMEM_FLOATS = OFF_SCR + NWARPS * SCR_FLOATS;   // 50856 -> 203424 B

// ---- f32x2 helpers ----
__device__ __forceinline__ u64 pk2(float lo, float hi) {
    u64 r; asm("mov.b64 %0,{%1,%2};" : "=l"(r) : "f"(lo), "f"(hi)); return r;
}
__device__ __forceinline__ u64 dup2(float v) { return pk2(v, v); }
__device__ __forceinline__ void un2(u64 v, float& a, float& b) {
    asm("mov.b64 {%0,%1},%2;" : "=f"(a), "=f"(b) : "l"(v));
}
__device__ __forceinline__ u64 f2fma(u64 a, u64 b, u64 c) {
    u64 d; asm("fma.rn.f32x2 %0,%1,%2,%3;" : "=l"(d) : "l"(a), "l"(b), "l"(c)); return d;
}
__device__ __forceinline__ u64 f2add(u64 a, u64 b) {
    u64 d; asm("add.rn.f32x2 %0,%1,%2;" : "=l"(d) : "l"(a), "l"(b)); return d;
}
__device__ __forceinline__ u64 f2mul(u64 a, u64 b) {
    u64 d; asm("mul.rn.f32x2 %0,%1,%2;" : "=l"(d) : "l"(a), "l"(b)); return d;
}
__device__ __forceinline__ float ex2f(float x) {
    float y; asm("ex2.approx.f32 %0,%1;" : "=f"(y) : "f"(x)); return y;
}
__device__ __forceinline__ float bfly_add(float v) {
    #pragma unroll
    for (int o = 16; o >= 1; o >>= 1) v += __shfl_xor_sync(FULLMASK, v, o);
    return v;
}

// layernorm on row-pairs: vlo = channels L (rows p,p+4), vhi = channels L+32
__device__ __forceinline__ void ln_pair(u64 vlo, u64 vhi, u64 glo, u64 ghi, u64 blo, u64 bhi,
                                        u64& xlo, u64& xhi) {
    float sa, sb; un2(f2add(vlo, vhi), sa, sb);
    sa = bfly_add(sa); sb = bfly_add(sb);
    u64 mun = f2mul(pk2(sa, sb), dup2(-1.0f / 64.0f));
    u64 dlo = f2add(vlo, mun), dhi = f2add(vhi, mun);
    float qa, qb; un2(f2fma(dlo, dlo, f2mul(dhi, dhi)), qa, qb);
    qa = bfly_add(qa); qb = bfly_add(qb);
    float ra = rsqrtf(fmaf(qa, 1.0f / 64.0f, 1e-5f));
    float rb = rsqrtf(fmaf(qb, 1.0f / 64.0f, 1e-5f));
    u64 rs = pk2(ra, rb);
    xlo = f2fma(f2mul(dlo, rs), glo, blo);
    xhi = f2fma(f2mul(dhi, rs), ghi, bhi);
}

__global__ void __launch_bounds__(NTHREADS, 1)
main_kernel(const float* __restrict__ prec, const int* __restrict__ topmask,
            const float* __restrict__ We, const float* __restrict__ be,
            const float* __restrict__ Wq, const float* __restrict__ Wk,
            const float* __restrict__ Wv, const float* __restrict__ Wo,
            const float* __restrict__ bo,
            const float* __restrict__ g1, const float* __restrict__ lb1,
            const float* __restrict__ W1, const float* __restrict__ b1,
            const float* __restrict__ W2, const float* __restrict__ b2,
            const float* __restrict__ g2, const float* __restrict__ lb2,
            float* __restrict__ out)
{
    extern __shared__ float sm[];
    const int tid = threadIdx.x;

    // ---- stage big weights ----
    {
        float4* d = (float4*)(sm + OFF_W1);
        const float4* s = (const float4*)W1;
        for (int i = tid; i < 16384 / 4; i += NTHREADS) d[i] = s[i];
    }
    for (int i = tid; i < 256 * 32; i += NTHREADS) {   // W2 pairs
        int j = i >> 5, l = i & 31;
        sm[OFF_W2P + i * 2]     = W2[j * 64 + l];
        sm[OFF_W2P + i * 2 + 1] = W2[j * 64 + 32 + l];
    }
    if (tid < 256) sm[OFF_B1 + tid] = b1[tid];
    if (tid < 128) sm[OFF_WE + tid] = We[tid];
    if (tid >= 128 && tid < 192) sm[OFF_BE + tid - 128] = be[tid - 128];
    if (tid >= 192 && tid < 224) {
        int t = tid - 192;
        float v;
        v = g1[t];       sm[OFF_DUP + 0 * 64 + 2 * t] = v; sm[OFF_DUP + 0 * 64 + 2 * t + 1] = v;
        v = g1[32 + t];  sm[OFF_DUP + 1 * 64 + 2 * t] = v; sm[OFF_DUP + 1 * 64 + 2 * t + 1] = v;
        v = lb1[t];      sm[OFF_DUP + 2 * 64 + 2 * t] = v; sm[OFF_DUP + 2 * 64 + 2 * t + 1] = v;
        v = lb1[32 + t]; sm[OFF_DUP + 3 * 64 + 2 * t] = v; sm[OFF_DUP + 3 * 64 + 2 * t + 1] = v;
        v = b2[t];       sm[OFF_DUP + 4 * 64 + 2 * t] = v; sm[OFF_DUP + 4 * 64 + 2 * t + 1] = v;
        v = b2[32 + t];  sm[OFF_DUP + 5 * 64 + 2 * t] = v; sm[OFF_DUP + 5 * 64 + 2 * t + 1] = v;
        v = g2[t];       sm[OFF_DUP + 6 * 64 + 2 * t] = v; sm[OFF_DUP + 6 * 64 + 2 * t + 1] = v;
        v = g2[32 + t];  sm[OFF_DUP + 7 * 64 + 2 * t] = v; sm[OFF_DUP + 7 * 64 + 2 * t + 1] = v;
        v = lb2[t];      sm[OFF_DUP + 8 * 64 + 2 * t] = v; sm[OFF_DUP + 8 * 64 + 2 * t + 1] = v;
        v = lb2[32 + t]; sm[OFF_DUP + 9 * 64 + 2 * t] = v; sm[OFF_DUP + 9 * 64 + 2 * t + 1] = v;
    }

    // ---- setup stage 1: combined QKV embed weights (temps in warp0/1 scratch) ----
    float* tWQ = sm + OFF_SCR;
    float* tWK = tWQ + 128;
    float* tWV = tWK + 128;
    float* tbQ = tWV + 128;
    float* tbK = tbQ + 64;
    float* tbV = tbK + 64;
    if (tid < 64) {
        int j = tid, h = j >> 4, d = j & 15;
        float q0 = 0.f, q1 = 0.f, k0 = 0.f, k1 = 0.f, v0 = 0.f, v1 = 0.f;
        float bq = 0.f, bk = 0.f, bv = 0.f;
        for (int e = 0; e < 16; e++) {
            float we0 = We[h * 16 + e];
            float we1 = We[64 + h * 16 + e];
            float bb  = be[h * 16 + e];
            float wq = Wq[e * 16 + d], wk = Wk[e * 16 + d], wv = Wv[e * 16 + d];
            q0 = fmaf(we0, wq, q0); q1 = fmaf(we1, wq, q1); bq = fmaf(bb, wq, bq);
            k0 = fmaf(we0, wk, k0); k1 = fmaf(we1, wk, k1); bk = fmaf(bb, wk, bk);
            v0 = fmaf(we0, wv, v0); v1 = fmaf(we1, wv, v1); bv = fmaf(bb, wv, bv);
        }
        tWQ[j] = q0; tWQ[64 + j] = q1; tbQ[j] = bq;
        tWK[j] = k0; tWK[64 + j] = k1; tbK[j] = bk;
        tWV[j] = v0; tWV[64 + j] = v1; tbV[j] = bv;
    }
    __syncthreads();

    // ---- setup stage 2: bilinear energy forms + folded Wo ----
    if (tid < 4) {
        const float SC = 0.125f * 1.4426950408889634f;
        int hh = tid;
        float m00=0,m01=0,m02=0,m10=0,m11=0,m12=0,m20=0,m21=0,m22=0;
        for (int dd = 0; dd < 16; dd++) {
            float Q0 = tWQ[hh*16+dd], Q1 = tWQ[64+hh*16+dd], BQ = tbQ[hh*16+dd];
            float K0 = tWK[hh*16+dd], K1 = tWK[64+hh*16+dd], BK = tbK[hh*16+dd];
            m00 += Q0*K0; m01 += Q0*K1; m02 += Q0*BK;
            m10 += Q1*K0; m11 += Q1*K1; m12 += Q1*BK;
            m20 += BQ*K0; m21 += BQ*K1; m22 += BQ*BK;
        }
        sm[OFF_M+hh*9+0]=m00*SC; sm[OFF_M+hh*9+1]=m01*SC; sm[OFF_M+hh*9+2]=m02*SC;
        sm[OFF_M+hh*9+3]=m10*SC; sm[OFF_M+hh*9+4]=m11*SC; sm[OFF_M+hh*9+5]=m12*SC;
        sm[OFF_M+hh*9+6]=m20*SC; sm[OFF_M+hh*9+7]=m21*SC; sm[OFF_M+hh*9+8]=m22*SC;
    }
    if (tid >= 64 && tid < 128) {
        int j = tid - 64;
        float kk = 0.f;
        for (int hh = 0; hh < 4; hh++) {
            float s0 = 0.f, s1 = 0.f;
            for (int dd = 0; dd < 16; dd++) {
                int row = hh * 16 + dd;
                float w = Wo[row * 64 + j];
                s0 = fmaf(tWV[row], w, s0);
                s1 = fmaf(tWV[64 + row], w, s1);
                kk = fmaf(tbV[row], w, kk);
            }
            sm[OFF_A0 + hh * 64 + j] = s0;
            sm[OFF_A1 + hh * 64 + j] = s1;
        }
        sm[OFF_K + j] = kk + bo[j];
    }
    __syncthreads();

    const int warp = tid >> 5;
    const int L = tid & 31;
    float* scr  = sm + OFF_SCR + warp * SCR_FLOATS;
    u64*   sxp  = (u64*)scr;             // [4][64]  x pairs, floats [0,512)
    u64*   shp  = (u64*)(scr + 512);     // [4][64]  h HALF-chunk pairs, floats [512,1024)
    float2* pkb = (float2*)scr;          // [8][33]  (px,py), floats [0,528) — aliases sxp/shp head
    u64*   uvb  = (u64*)scr;             // [32] (û,v̂) — aliases sxp head

    // hoisted per-lane constants
    const float we0l = sm[OFF_WE + L],      we1l = sm[OFF_WE + 64 + L],  bel = sm[OFF_BE + L];
    const float we0h = sm[OFF_WE + 32 + L], we1h = sm[OFF_WE + 96 + L], beh = sm[OFF_BE + 32 + L];
    u64 a0p[4], a1p[4];
    #pragma unroll
    for (int h = 0; h < 4; h++) {
        a0p[h] = pk2(sm[OFF_A0 + h * 64 + L], sm[OFF_A0 + h * 64 + 32 + L]);
        a1p[h] = pk2(sm[OFF_A1 + h * 64 + L], sm[OFF_A1 + h * 64 + 32 + L]);
    }
    const u64 kv2 = pk2(sm[OFF_K + L], sm[OFF_K + 32 + L]);
    const int rr = L >> 2, hh = L & 3;
    const int myhalf = L >> 4;            // 0 for lanes 0-15, 1 for 16-31
    const int lhalf  = L & 15;

    const int g0 = warp * gridDim.x + blockIdx.x;
    const int gstride = gridDim.x * NWARPS;

    for (int g = g0; g < NGROUPS; g += gstride) {
        const int m0 = g * 8;
        const int bb = m0 / 192;
        const int mk = topmask[bb * 32 + L];
        const unsigned mkbits = __ballot_sync(FULLMASK, mk != 0);
        const int kqbase = m0 & 31;

        // ---- stage keys (float2, padded stride 33) + qres via shuffle ----
        float qres_l[8], qres_h[8];
        #pragma unroll
        for (int r = 0; r < 8; r++) {
            float2 p = ((const float2*)prec)[(m0 + r) * 32 + L];
            pkb[r * 33 + L] = p;
            const float pq0 = __shfl_sync(FULLMASK, p.x, kqbase + r);
            const float pq1 = __shfl_sync(FULLMASK, p.y, kqbase + r);
            qres_l[r] = fmaf(pq0, we0l, fmaf(pq1, we1l, bel));
            qres_h[r] = fmaf(pq0, we0h, fmaf(pq1, we1h, beh));
        }
        __syncwarp();

        // ---- transposed softmax: lane owns (row rr, head hh) ----
        {
            const float2 pq = pkb[rr * 33 + kqbase + rr];
            const float* Mh = sm + OFF_M + hh * 9;
            const float Ah = fmaf(pq.y, Mh[3], fmaf(pq.x, Mh[0], Mh[6]));
            const float Bh = fmaf(pq.y, Mh[4], fmaf(pq.x, Mh[1], Mh[7]));
            const float Ch = fmaf(pq.y, Mh[5], fmaf(pq.x, Mh[2], Mh[8]));
            float s = 0.f, u = 0.f, v = 0.f;
            const float2* row = &pkb[rr * 33];
            #pragma unroll 8
            for (int k = 0; k < 32; k++) {
                float2 t = row[k];
                float e = fmaf(Ah, t.x, fmaf(Bh, t.y, Ch));
                float p = ((mkbits >> k) & 1u) ? ex2f(e) : 0.0f;
                s += p;
                u = fmaf(p, t.x, u);
                v = fmaf(p, t.y, v);
            }
            const float inv = __fdividef(1.0f, s);
            __syncwarp();                 // all pkb reads done before uvb overwrite
            uvb[L] = pk2(u * inv, v * inv);
        }
        __syncwarp();

        // ---- folded attention output ao (u64 = (ch L, ch L+32)) ----
        u64 ao[8];
        #pragma unroll
        for (int r = 0; r < 8; r++) {
            u64 a = kv2;
            #pragma unroll
            for (int h = 0; h < 4; h++) {
                const float2 uv = ((const float2*)uvb)[4 * r + h];
                a = f2fma(dup2(uv.x), a0p[h], f2fma(dup2(uv.y), a1p[h], a));
            }
            ao[r] = a;
        }
        __syncwarp();   // uvb reads done before x stores overwrite

        // ---- LN1 -> x pairs; store to smem for broadcast use in C ----
        u64 x_lo[4], x_hi[4];
        {
            const u64 g1l = *(const u64*)&sm[OFF_DUP + 0 * 64 + 2 * L];
            const u64 g1h = *(const u64*)&sm[OFF_DUP + 1 * 64 + 2 * L];
            const u64 l1l = *(const u64*)&sm[OFF_DUP + 2 * 64 + 2 * L];
            const u64 l1h = *(const u64*)&sm[OFF_DUP + 3 * 64 + 2 * L];
            #pragma unroll
            for (int p = 0; p < 4; p++) {
                float al, ah, bl, bhv;
                un2(ao[p], al, ah); un2(ao[p + 4], bl, bhv);
                u64 vlo = pk2(al + qres_l[p], bl + qres_l[p + 4]);
                u64 vhi = pk2(ah + qres_h[p], bhv + qres_h[p + 4]);
                ln_pair(vlo, vhi, g1l, g1h, l1l, l1h, x_lo[p], x_hi[p]);
            }
        }
        #pragma unroll
        for (int p = 0; p < 4; p++) {
            sxp[p * 64 + L]      = x_lo[p];
            sxp[p * 64 + 32 + L] = x_hi[p];
        }
        __syncwarp();

        // ---- FFN: per 128-ch chunk: C, then D in two 64-ch halves ----
        u64 y_lo[4], y_hi[4];
        {
            const u64 b2l = *(const u64*)&sm[OFF_DUP + 4 * 64 + 2 * L];
            const u64 b2h = *(const u64*)&sm[OFF_DUP + 5 * 64 + 2 * L];
            #pragma unroll
            for (int p = 0; p < 4; p++) { y_lo[p] = b2l; y_hi[p] = b2h; }
        }
        #pragma unroll 1
        for (int cc = 0; cc < 2; cc++) {
            // C: thread owns channels cc*128 + 4L + t
            u64 hacc[4][4];
            {
                const float4 b1v = *(const float4*)&sm[OFF_B1 + cc * 128 + 4 * L];
                const u64 i0 = dup2(b1v.x), i1 = dup2(b1v.y), i2 = dup2(b1v.z), i3 = dup2(b1v.w);
                #pragma unroll
                for (int p = 0; p < 4; p++) { hacc[p][0]=i0; hacc[p][1]=i1; hacc[p][2]=i2; hacc[p][3]=i3; }
            }
            const float* W1c = sm + OFF_W1 + cc * 128 + 4 * L;
            #pragma unroll 4
            for (int j = 0; j < 64; j++) {
                const float4 w = *(const float4*)&W1c[j * 256];
                const u64 w0 = dup2(w.x), w1 = dup2(w.y), w2 = dup2(w.z), w3 = dup2(w.w);
                #pragma unroll
                for (int p = 0; p < 4; p++) {
                    const u64 xj = sxp[p * 64 + j];          // LDS.64 broadcast
                    hacc[p][0] = f2fma(xj, w0, hacc[p][0]);
                    hacc[p][1] = f2fma(xj, w1, hacc[p][1]);
                    hacc[p][2] = f2fma(xj, w2, hacc[p][2]);
                    hacc[p][3] = f2fma(xj, w3, hacc[p][3]);
                }
            }
            // relu in place
            #pragma unroll
            for (int p = 0; p < 4; p++) {
                #pragma unroll
                for (int t = 0; t < 4; t++) {
                    float a, b; un2(hacc[p][t], a, b);
                    hacc[p][t] = pk2(fmaxf(a, 0.0f), fmaxf(b, 0.0f));
                }
            }
            // D in two 64-channel halves (shp holds one half at a time)
            #pragma unroll 1
            for (int s = 0; s < 2; s++) {
                if (myhalf == s) {
                    #pragma unroll
                    for (int p = 0; p < 4; p++) {
                        #pragma unroll
                        for (int t = 0; t < 4; t++)
                            shp[p * 64 + 4 * lhalf + t] = hacc[p][t];
                    }
                }
                __syncwarp();
                const float* W2h = sm + OFF_W2P + (cc * 128 + s * 64) * 64;  // pair layout
                #pragma unroll 4
                for (int u = 0; u < 32; u++) {
                    const int jj = 2 * u;
                    const u64 wa = *(const u64*)&W2h[jj * 64 + 2 * L];        // (W2[j][L], W2[j][L+32])
                    const u64 wb = *(const u64*)&W2h[(jj + 1) * 64 + 2 * L];
                    float wal, wah, wbl, wbh; un2(wa, wal, wah); un2(wb, wbl, wbh);
                    const u64 wal2 = dup2(wal), wah2 = dup2(wah), wbl2 = dup2(wbl), wbh2 = dup2(wbh);
                    #pragma unroll
                    for (int p = 0; p < 4; p++) {
                        ulonglong2 h2 = *(const ulonglong2*)&shp[p * 64 + jj];  // LDS.128 broadcast
                        y_lo[p] = f2fma(h2.x, wal2, y_lo[p]);
                        y_hi[p] = f2fma(h2.x, wah2, y_hi[p]);
                        y_lo[p] = f2fma(h2.y, wbl2, y_lo[p]);
                        y_hi[p] = f2fma(h2.y, wbh2, y_hi[p]);
                    }
                }
                __syncwarp();
            }
        }

        // ---- LN2 + store ----
        {
            const u64 g2l = *(const u64*)&sm[OFF_DUP + 6 * 64 + 2 * L];
            const u64 g2h = *(const u64*)&sm[OFF_DUP + 7 * 64 + 2 * L];
            const u64 l2l = *(const u64*)&sm[OFF_DUP + 8 * 64 + 2 * L];
            const u64 l2h = *(const u64*)&sm[OFF_DUP + 9 * 64 + 2 * L];
            #pragma unroll
            for (int p = 0; p < 4; p++) {
                u64 vlo = f2add(y_lo[p], x_lo[p]);
                u64 vhi = f2add(y_hi[p], x_hi[p]);
                u64 olo, ohi;
                ln_pair(vlo, vhi, g2l, g2h, l2l, l2h, olo, ohi);
                float a, b, c, d;
                un2(olo, a, b); un2(ohi, c, d);
                out[(m0 + p) * 64 + L]           = a;
                out[(m0 + p + 4) * 64 + L]       = b;
                out[(m0 + p) * 64 + 32 + L]      = c;
                out[(m0 + p + 4) * 64 + 32 + L]  = d;
            }
        }
        __syncwarp();   // shp/sxp reads done before next group's pkb stores
    }
}

extern "C" void kernel_launch(void* const* d_in, const int* in_sizes, int n_in,
                              void* d_out, int out_size) {
    const float* prec = (const float*)d_in[0];
    const int*   msk  = (const int*)d_in[1];
    const float* We   = (const float*)d_in[2];
    const float* be   = (const float*)d_in[3];
    const float* Wq   = (const float*)d_in[4];
    const float* Wk   = (const float*)d_in[5];
    const float* Wv   = (const float*)d_in[6];
    const float* Wo   = (const float*)d_in[7];
    const float* bo   = (const float*)d_in[8];
    const float* g1   = (const float*)d_in[9];
    const float* lb1  = (const float*)d_in[10];
    const float* W1   = (const float*)d_in[11];
    const float* b1   = (const float*)d_in[12];
    const float* W2   = (const float*)d_in[13];
    const float* b2   = (const float*)d_in[14];
    const float* g2   = (const float*)d_in[15];
    const float* lb2  = (const float*)d_in[16];
    float* out = (float*)d_out;

    const int smem_bytes = SMEM_FLOATS * (int)sizeof(float);
    cudaFuncSetAttribute(main_kernel, cudaFuncAttributeMaxDynamicSharedMemorySize, smem_bytes);

    int nsm = 148;
    cudaDeviceGetAttribute(&nsm, cudaDevAttrMultiProcessorCount, 0);

    main_kernel<<<nsm, NTHREADS, smem_bytes>>>(prec, msk, We, be, Wq, Wk, Wv, Wo, bo,
                                               g1, lb1, W1, b1, W2, b2, g2, lb2, out);
}

// round 8
// speedup vs baseline: 1.1214x; 1.1214x over previous
#include <cuda_runtime.h>

typedef unsigned long long u64;
#define FULLMASK 0xffffffffu

constexpr int NWARPS   = 12;
constexpr int NTHREADS = NWARPS * 32;     // 384
constexpr int NGROUPS  = 24576 / 8;       // 3072 groups of 8 rows

// ---- shared memory layout (float offsets) ----
constexpr int OFF_W1  = 0;          // [64][256]
constexpr int OFF_W2P = 16384;      // float2[256][32]: (W2[j][L], W2[j][L+32])
constexpr int OFF_B1  = 32768;      // [256]
constexpr int OFF_WE  = 33024;      // [2][64]
constexpr int OFF_BE  = 33152;      // [64]
constexpr int OFF_M   = 33216;      // [4][9] bilinear energy coeffs (x 0.125*log2e), pad 40
constexpr int OFF_A0  = 33256;      // [4][64]  WeV0 @ Wo per head
constexpr int OFF_A1  = 33512;      // [4][64]
constexpr int OFF_K   = 33768;      // [64]     beV @ Wo + bo
constexpr int OFF_DUP = 33832;      // 10 x 64: g1lo,g1hi,lb1lo,lb1hi,b2lo,b2hi,g2lo,g2hi,lb2lo,lb2hi
constexpr int OFF_SCR = 34472;      // per-warp scratch
constexpr int SCR_FLOATS = 1568;    // x pairs [0,512) + h/pkb region [512,1568)
constexpr int SMEM_FLOATS = OFF_SCR + NWARPS * SCR_FLOATS;   // 53288 -> 213152 B

// ---- f32x2 helpers ----
__device__ __forceinline__ u64 pk2(float lo, float hi) {
    u64 r; asm("mov.b64 %0,{%1,%2};" : "=l"(r) : "f"(lo), "f"(hi)); return r;
}
__device__ __forceinline__ u64 dup2(float v) { return pk2(v, v); }
__device__ __forceinline__ void un2(u64 v, float& a, float& b) {
    asm("mov.b64 {%0,%1},%2;" : "=f"(a), "=f"(b) : "l"(v));
}
__device__ __forceinline__ u64 f2fma(u64 a, u64 b, u64 c) {
    u64 d; asm("fma.rn.f32x2 %0,%1,%2,%3;" : "=l"(d) : "l"(a), "l"(b), "l"(c)); return d;
}
__device__ __forceinline__ u64 f2add(u64 a, u64 b) {
    u64 d; asm("add.rn.f32x2 %0,%1,%2;" : "=l"(d) : "l"(a), "l"(b)); return d;
}
__device__ __forceinline__ u64 f2mul(u64 a, u64 b) {
    u64 d; asm("mul.rn.f32x2 %0,%1,%2;" : "=l"(d) : "l"(a), "l"(b)); return d;
}
__device__ __forceinline__ float ex2f(float x) {
    float y; asm("ex2.approx.f32 %0,%1;" : "=f"(y) : "f"(x)); return y;
}
__device__ __forceinline__ float bfly_add(float v) {
    #pragma unroll
    for (int o = 16; o >= 1; o >>= 1) v += __shfl_xor_sync(FULLMASK, v, o);
    return v;
}

// layernorm on row-pairs: vlo = channels L (rows p,p+4), vhi = channels L+32
__device__ __forceinline__ void ln_pair(u64 vlo, u64 vhi, u64 glo, u64 ghi, u64 blo, u64 bhi,
                                        u64& xlo, u64& xhi) {
    float sa, sb; un2(f2add(vlo, vhi), sa, sb);
    sa = bfly_add(sa); sb = bfly_add(sb);
    u64 mun = f2mul(pk2(sa, sb), dup2(-1.0f / 64.0f));
    u64 dlo = f2add(vlo, mun), dhi = f2add(vhi, mun);
    float qa, qb; un2(f2fma(dlo, dlo, f2mul(dhi, dhi)), qa, qb);
    qa = bfly_add(qa); qb = bfly_add(qb);
    float ra = rsqrtf(fmaf(qa, 1.0f / 64.0f, 1e-5f));
    float rb = rsqrtf(fmaf(qb, 1.0f / 64.0f, 1e-5f));
    u64 rs = pk2(ra, rb);
    xlo = f2fma(f2mul(dlo, rs), glo, blo);
    xhi = f2fma(f2mul(dhi, rs), ghi, bhi);
}

__global__ void __launch_bounds__(NTHREADS, 1)
main_kernel(const float* __restrict__ prec, const int* __restrict__ topmask,
            const float* __restrict__ We, const float* __restrict__ be,
            const float* __restrict__ Wq, const float* __restrict__ Wk,
            const float* __restrict__ Wv, const float* __restrict__ Wo,
            const float* __restrict__ bo,
            const float* __restrict__ g1, const float* __restrict__ lb1,
            const float* __restrict__ W1, const float* __restrict__ b1,
            const float* __restrict__ W2, const float* __restrict__ b2,
            const float* __restrict__ g2, const float* __restrict__ lb2,
            float* __restrict__ out)
{
    extern __shared__ float sm[];
    const int tid = threadIdx.x;

    // ---- stage big weights ----
    {
        float4* d = (float4*)(sm + OFF_W1);
        const float4* s = (const float4*)W1;
        for (int i = tid; i < 16384 / 4; i += NTHREADS) d[i] = s[i];
    }
    for (int i = tid; i < 256 * 32; i += NTHREADS) {   // W2 pairs
        int j = i >> 5, l = i & 31;
        sm[OFF_W2P + i * 2]     = W2[j * 64 + l];
        sm[OFF_W2P + i * 2 + 1] = W2[j * 64 + 32 + l];
    }
    if (tid < 256) sm[OFF_B1 + tid] = b1[tid];
    if (tid < 128) sm[OFF_WE + tid] = We[tid];
    if (tid >= 128 && tid < 192) sm[OFF_BE + tid - 128] = be[tid - 128];
    if (tid >= 192 && tid < 224) {
        int t = tid - 192;
        float v;
        v = g1[t];       sm[OFF_DUP + 0 * 64 + 2 * t] = v; sm[OFF_DUP + 0 * 64 + 2 * t + 1] = v;
        v = g1[32 + t];  sm[OFF_DUP + 1 * 64 + 2 * t] = v; sm[OFF_DUP + 1 * 64 + 2 * t + 1] = v;
        v = lb1[t];      sm[OFF_DUP + 2 * 64 + 2 * t] = v; sm[OFF_DUP + 2 * 64 + 2 * t + 1] = v;
        v = lb1[32 + t]; sm[OFF_DUP + 3 * 64 + 2 * t] = v; sm[OFF_DUP + 3 * 64 + 2 * t + 1] = v;
        v = b2[t];       sm[OFF_DUP + 4 * 64 + 2 * t] = v; sm[OFF_DUP + 4 * 64 + 2 * t + 1] = v;
        v = b2[32 + t];  sm[OFF_DUP + 5 * 64 + 2 * t] = v; sm[OFF_DUP + 5 * 64 + 2 * t + 1] = v;
        v = g2[t];       sm[OFF_DUP + 6 * 64 + 2 * t] = v; sm[OFF_DUP + 6 * 64 + 2 * t + 1] = v;
        v = g2[32 + t];  sm[OFF_DUP + 7 * 64 + 2 * t] = v; sm[OFF_DUP + 7 * 64 + 2 * t + 1] = v;
        v = lb2[t];      sm[OFF_DUP + 8 * 64 + 2 * t] = v; sm[OFF_DUP + 8 * 64 + 2 * t + 1] = v;
        v = lb2[32 + t]; sm[OFF_DUP + 9 * 64 + 2 * t] = v; sm[OFF_DUP + 9 * 64 + 2 * t + 1] = v;
    }

    // ---- setup stage 1: combined QKV embed weights (temps in warp0/1 scratch) ----
    float* tWQ = sm + OFF_SCR;
    float* tWK = tWQ + 128;
    float* tWV = tWK + 128;
    float* tbQ = tWV + 128;
    float* tbK = tbQ + 64;
    float* tbV = tbK + 64;
    if (tid < 64) {
        int j = tid, h = j >> 4, d = j & 15;
        float q0 = 0.f, q1 = 0.f, k0 = 0.f, k1 = 0.f, v0 = 0.f, v1 = 0.f;
        float bq = 0.f, bk = 0.f, bv = 0.f;
        for (int e = 0; e < 16; e++) {
            float we0 = We[h * 16 + e];
            float we1 = We[64 + h * 16 + e];
            float bb  = be[h * 16 + e];
            float wq = Wq[e * 16 + d], wk = Wk[e * 16 + d], wv = Wv[e * 16 + d];
            q0 = fmaf(we0, wq, q0); q1 = fmaf(we1, wq, q1); bq = fmaf(bb, wq, bq);
            k0 = fmaf(we0, wk, k0); k1 = fmaf(we1, wk, k1); bk = fmaf(bb, wk, bk);
            v0 = fmaf(we0, wv, v0); v1 = fmaf(we1, wv, v1); bv = fmaf(bb, wv, bv);
        }
        tWQ[j] = q0; tWQ[64 + j] = q1; tbQ[j] = bq;
        tWK[j] = k0; tWK[64 + j] = k1; tbK[j] = bk;
        tWV[j] = v0; tWV[64 + j] = v1; tbV[j] = bv;
    }
    __syncthreads();

    // ---- setup stage 2: bilinear energy forms + folded Wo ----
    if (tid < 4) {
        const float SC = 0.125f * 1.4426950408889634f;   // 1/sqrt(E) + log2e fold
        int hh = tid;
        float m00=0,m01=0,m02=0,m10=0,m11=0,m12=0,m20=0,m21=0,m22=0;
        for (int dd = 0; dd < 16; dd++) {
            float Q0 = tWQ[hh*16+dd], Q1 = tWQ[64+hh*16+dd], BQ = tbQ[hh*16+dd];
            float K0 = tWK[hh*16+dd], K1 = tWK[64+hh*16+dd], BK = tbK[hh*16+dd];
            m00 += Q0*K0; m01 += Q0*K1; m02 += Q0*BK;
            m10 += Q1*K0; m11 += Q1*K1; m12 += Q1*BK;
            m20 += BQ*K0; m21 += BQ*K1; m22 += BQ*BK;
        }
        sm[OFF_M+hh*9+0]=m00*SC; sm[OFF_M+hh*9+1]=m01*SC; sm[OFF_M+hh*9+2]=m02*SC;
        sm[OFF_M+hh*9+3]=m10*SC; sm[OFF_M+hh*9+4]=m11*SC; sm[OFF_M+hh*9+5]=m12*SC;
        sm[OFF_M+hh*9+6]=m20*SC; sm[OFF_M+hh*9+7]=m21*SC; sm[OFF_M+hh*9+8]=m22*SC;
    }
    if (tid >= 64 && tid < 128) {
        int j = tid - 64;
        float kk = 0.f;
        for (int hh = 0; hh < 4; hh++) {
            float s0 = 0.f, s1 = 0.f;
            for (int dd = 0; dd < 16; dd++) {
                int row = hh * 16 + dd;
                float w = Wo[row * 64 + j];
                s0 = fmaf(tWV[row], w, s0);
                s1 = fmaf(tWV[64 + row], w, s1);
                kk = fmaf(tbV[row], w, kk);
            }
            sm[OFF_A0 + hh * 64 + j] = s0;
            sm[OFF_A1 + hh * 64 + j] = s1;
        }
        sm[OFF_K + j] = kk + bo[j];
    }
    __syncthreads();

    const int warp = tid >> 5;
    const int L = tid & 31;
    float* scr = sm + OFF_SCR + warp * SCR_FLOATS;
    u64* sxp    = (u64*)scr;             // [4][64]  x pairs, floats [0,512)
    u64* shp    = (u64*)(scr + 512);     // [4][128] h chunk pairs, floats [512,1536)
    float4* pkb = (float4*)(scr + 512);  // [8][33]  (px, py, madd, 0), floats [512,1568) — aliases shp
    u64* uvb    = (u64*)scr;             // [32] (û, v̂) — aliases sxp head

    // hoisted per-lane constants
    const float we0l = sm[OFF_WE + L],      we1l = sm[OFF_WE + 64 + L],  bel = sm[OFF_BE + L];
    const float we0h = sm[OFF_WE + 32 + L], we1h = sm[OFF_WE + 96 + L], beh = sm[OFF_BE + 32 + L];
    u64 a0p[4], a1p[4];
    #pragma unroll
    for (int h = 0; h < 4; h++) {
        a0p[h] = pk2(sm[OFF_A0 + h * 64 + L], sm[OFF_A0 + h * 64 + 32 + L]);
        a1p[h] = pk2(sm[OFF_A1 + h * 64 + L], sm[OFF_A1 + h * 64 + 32 + L]);
    }
    const u64 kv2 = pk2(sm[OFF_K + L], sm[OFF_K + 32 + L]);
    const int rr = L >> 2, hh = L & 3;
    float Mh[9];
    #pragma unroll
    for (int i = 0; i < 9; i++) Mh[i] = sm[OFF_M + hh * 9 + i];

    const int g0 = warp * gridDim.x + blockIdx.x;
    const int gstride = gridDim.x * NWARPS;

    for (int g = g0; g < NGROUPS; g += gstride) {
        const int m0 = g * 8;
        const int bb = m0 / 192;             // 8 | 192: group stays in one batch row
        const int mk = topmask[bb * 32 + L];
        const float madd = (mk != 0) ? 0.0f : -4e18f;
        const int kqbase = m0 & 31;

        // ---- stage keys: (px, py, madd) per key, per row (stride-33, conflict-free) ----
        #pragma unroll
        for (int r = 0; r < 8; r++) {
            float2 p = ((const float2*)prec)[(m0 + r) * 32 + L];
            pkb[r * 33 + L] = make_float4(p.x, p.y, madd, 0.0f);
        }
        __syncwarp();

        // ---- transposed softmax: lane owns (row rr, head hh) ----
        {
            const float2 pq = *(const float2*)&pkb[rr * 33 + kqbase + rr];
            const float Ah = fmaf(pq.y, Mh[3], fmaf(pq.x, Mh[0], Mh[6]));
            const float Bh = fmaf(pq.y, Mh[4], fmaf(pq.x, Mh[1], Mh[7]));
            const float Ch = fmaf(pq.y, Mh[5], fmaf(pq.x, Mh[2], Mh[8]));
            float s = 0.f, u = 0.f, v = 0.f;
            const float4* row = &pkb[rr * 33];
            #pragma unroll 8
            for (int k = 0; k < 32; k++) {
                float4 t = row[k];
                float e = fmaf(Ah, t.x, fmaf(Bh, t.y, Ch)) + t.z;
                float p = ex2f(e);
                s += p;
                u = fmaf(p, t.x, u);
                v = fmaf(p, t.y, v);
            }
            const float inv = __fdividef(1.0f, s);
            __syncwarp();                 // pkb reads for softmax done (qres still reads below — different region than uvb)
            uvb[L] = pk2(u * inv, v * inv);
        }
        __syncwarp();

        // ---- qres + folded attention output ao (per row) ----
        float qres_l[8], qres_h[8];
        u64 ao[8];
        #pragma unroll
        for (int r = 0; r < 8; r++) {
            const float2 pq = *(const float2*)&pkb[r * 33 + kqbase + r];
            qres_l[r] = fmaf(pq.x, we0l, fmaf(pq.y, we1l, bel));
            qres_h[r] = fmaf(pq.x, we0h, fmaf(pq.y, we1h, beh));
            u64 a = kv2;
            #pragma unroll
            for (int h = 0; h < 4; h++) {
                const float2 uv = ((const float2*)uvb)[4 * r + h];
                a = f2fma(dup2(uv.x), a0p[h], f2fma(dup2(uv.y), a1p[h], a));
            }
            ao[r] = a;
        }
        __syncwarp();     // all uvb/pkb reads done before x / h stores overwrite those regions

        // ---- LN1 -> x pairs; store to smem for broadcast use in C ----
        u64 x_lo[4], x_hi[4];
        {
            const u64 g1l = *(const u64*)&sm[OFF_DUP + 0 * 64 + 2 * L];
            const u64 g1h = *(const u64*)&sm[OFF_DUP + 1 * 64 + 2 * L];
            const u64 l1l = *(const u64*)&sm[OFF_DUP + 2 * 64 + 2 * L];
            const u64 l1h = *(const u64*)&sm[OFF_DUP + 3 * 64 + 2 * L];
            #pragma unroll
            for (int p = 0; p < 4; p++) {
                float al, ah, bl, bhv;
                un2(ao[p], al, ah); un2(ao[p + 4], bl, bhv);
                u64 vlo = pk2(al + qres_l[p], bl + qres_l[p + 4]);
                u64 vhi = pk2(ah + qres_h[p], bhv + qres_h[p + 4]);
                ln_pair(vlo, vhi, g1l, g1h, l1l, l1h, x_lo[p], x_hi[p]);
            }
        }
        #pragma unroll
        for (int p = 0; p < 4; p++) {
            sxp[p * 64 + L]      = x_lo[p];
            sxp[p * 64 + 32 + L] = x_hi[p];
        }
        __syncwarp();

        // ---- Phase C: h = relu(x @ W1 + b1), all 8 owned channels in one pass ----
        u64 hacc[4][8];
        {
            const float4 b1a = *(const float4*)&sm[OFF_B1 + 4 * L];
            const float4 b1b = *(const float4*)&sm[OFF_B1 + 128 + 4 * L];
            const u64 i0 = dup2(b1a.x), i1 = dup2(b1a.y), i2 = dup2(b1a.z), i3 = dup2(b1a.w);
            const u64 i4 = dup2(b1b.x), i5 = dup2(b1b.y), i6 = dup2(b1b.z), i7 = dup2(b1b.w);
            #pragma unroll
            for (int p = 0; p < 4; p++) {
                hacc[p][0]=i0; hacc[p][1]=i1; hacc[p][2]=i2; hacc[p][3]=i3;
                hacc[p][4]=i4; hacc[p][5]=i5; hacc[p][6]=i6; hacc[p][7]=i7;
            }
        }
        #pragma unroll 4
        for (int j = 0; j < 64; j++) {
            const float4 wa = *(const float4*)&sm[OFF_W1 + j * 256 + 4 * L];
            const float4 wb = *(const float4*)&sm[OFF_W1 + j * 256 + 128 + 4 * L];
            const u64 w0 = dup2(wa.x), w1 = dup2(wa.y), w2 = dup2(wa.z), w3 = dup2(wa.w);
            const u64 w4 = dup2(wb.x), w5 = dup2(wb.y), w6 = dup2(wb.z), w7 = dup2(wb.w);
            #pragma unroll
            for (int p = 0; p < 4; p++) {
                const u64 xj = sxp[p * 64 + j];
                hacc[p][0] = f2fma(xj, w0, hacc[p][0]);
                hacc[p][1] = f2fma(xj, w1, hacc[p][1]);
                hacc[p][2] = f2fma(xj, w2, hacc[p][2]);
                hacc[p][3] = f2fma(xj, w3, hacc[p][3]);
                hacc[p][4] = f2fma(xj, w4, hacc[p][4]);
                hacc[p][5] = f2fma(xj, w5, hacc[p][5]);
                hacc[p][6] = f2fma(xj, w6, hacc[p][6]);
                hacc[p][7] = f2fma(xj, w7, hacc[p][7]);
            }
        }

        // ---- Phase D: y = h @ W2 + b2, chunked, W2 pre-paired ----
        u64 y_lo[4], y_hi[4];
        {
            const u64 b2l = *(const u64*)&sm[OFF_DUP + 4 * 64 + 2 * L];
            const u64 b2h = *(const u64*)&sm[OFF_DUP + 5 * 64 + 2 * L];
            #pragma unroll
            for (int p = 0; p < 4; p++) { y_lo[p] = b2l; y_hi[p] = b2h; }
        }
        #pragma unroll 1
        for (int cc = 0; cc < 2; cc++) {
            // relu + store this chunk (hacc[.][cc*4 + t] = channels cc*128 + 4L + t)
            #pragma unroll
            for (int p = 0; p < 4; p++) {
                #pragma unroll
                for (int t = 0; t < 4; t++) {
                    float a, b; un2(hacc[p][cc * 4 + t], a, b);
                    a = fmaxf(a, 0.0f); b = fmaxf(b, 0.0f);
                    shp[p * 128 + 4 * L + t] = pk2(a, b);
                }
            }
            __syncwarp();
            const float* W2c = sm + OFF_W2P + cc * 128 * 64;   // float2[128][32] region
            #pragma unroll 4
            for (int u = 0; u < 64; u++) {
                const int jj = 2 * u;
                const u64 wa = *(const u64*)&W2c[jj * 64 + 2 * L];        // (W2[j][L], W2[j][L+32])
                const u64 wb = *(const u64*)&W2c[(jj + 1) * 64 + 2 * L];
                float wal, wah, wbl, wbh; un2(wa, wal, wah); un2(wb, wbl, wbh);
                const u64 wal2 = dup2(wal), wah2 = dup2(wah), wbl2 = dup2(wbl), wbh2 = dup2(wbh);
                #pragma unroll
                for (int p = 0; p < 4; p++) {
                    ulonglong2 h2v = *(const ulonglong2*)&shp[p * 128 + jj];  // LDS.128 broadcast
                    y_lo[p] = f2fma(h2v.x, wal2, y_lo[p]);
                    y_hi[p] = f2fma(h2v.x, wah2, y_hi[p]);
                    y_lo[p] = f2fma(h2v.y, wbl2, y_lo[p]);
                    y_hi[p] = f2fma(h2v.y, wbh2, y_hi[p]);
                }
            }
            __syncwarp();
        }

        // ---- LN2 + store ----
        {
            const u64 g2l = *(const u64*)&sm[OFF_DUP + 6 * 64 + 2 * L];
            const u64 g2h = *(const u64*)&sm[OFF_DUP + 7 * 64 + 2 * L];
            const u64 l2l = *(const u64*)&sm[OFF_DUP + 8 * 64 + 2 * L];
            const u64 l2h = *(const u64*)&sm[OFF_DUP + 9 * 64 + 2 * L];
            #pragma unroll
            for (int p = 0; p < 4; p++) {
                u64 vlo = f2add(y_lo[p], x_lo[p]);
                u64 vhi = f2add(y_hi[p], x_hi[p]);
                u64 olo, ohi;
                ln_pair(vlo, vhi, g2l, g2h, l2l, l2h, olo, ohi);
                float a, b, c, d;
                un2(olo, a, b); un2(ohi, c, d);
                out[(m0 + p) * 64 + L]           = a;
                out[(m0 + p + 4) * 64 + L]       = b;
                out[(m0 + p) * 64 + 32 + L]      = c;
                out[(m0 + p + 4) * 64 + 32 + L]  = d;
            }
        }
        __syncwarp();   // shp/sxp reads done before next group's pkb stores
    }
}

extern "C" void kernel_launch(void* const* d_in, const int* in_sizes, int n_in,
                              void* d_out, int out_size) {
    const float* prec = (const float*)d_in[0];
    const int*   msk  = (const int*)d_in[1];
    const float* We   = (const float*)d_in[2];
    const float* be   = (const float*)d_in[3];
    const float* Wq   = (const float*)d_in[4];
    const float* Wk   = (const float*)d_in[5];
    const float* Wv   = (const float*)d_in[6];
    const float* Wo   = (const float*)d_in[7];
    const float* bo   = (const float*)d_in[8];
    const float* g1   = (const float*)d_in[9];
    const float* lb1  = (const float*)d_in[10];
    const float* W1   = (const float*)d_in[11];
    const float* b1   = (const float*)d_in[12];
    const float* W2   = (const float*)d_in[13];
    const float* b2   = (const float*)d_in[14];
    const float* g2   = (const float*)d_in[15];
    const float* lb2  = (const float*)d_in[16];
    float* out = (float*)d_out;

    const int smem_bytes = SMEM_FLOATS * (int)sizeof(float);
    cudaFuncSetAttribute(main_kernel, cudaFuncAttributeMaxDynamicSharedMemorySize, smem_bytes);

    int nsm = 148;
    cudaDeviceGetAttribute(&nsm, cudaDevAttrMultiProcessorCount, 0);

    main_kernel<<<nsm, NTHREADS, smem_bytes>>>(prec, msk, We, be, Wq, Wk, Wv, Wo, bo,
                                               g1, lb1, W1, b1, W2, b2, g2, lb2, out);
}

// round 9
// speedup vs baseline: 1.1354x; 1.0125x over previous
#include <cuda_runtime.h>

typedef unsigned long long u64;
#define FULLMASK 0xffffffffu

constexpr int NWARPS   = 11;
constexpr int NTHREADS = NWARPS * 32;     // 352
constexpr int NGROUPS  = 24576 / 8;       // 3072 groups of 8 rows

// ---- shared memory layout (float offsets) ----
constexpr int OFF_W1  = 0;          // [64][256]
constexpr int OFF_W2P = 16384;      // float2[256][32]: (W2[j][L], W2[j][L+32])
constexpr int OFF_B1  = 32768;      // [256]
constexpr int OFF_WE  = 33024;      // [2][64]
constexpr int OFF_BE  = 33152;      // [64]
constexpr int OFF_M   = 33216;      // [4][9] bilinear energy coeffs (x 0.125*log2e), pad 40
constexpr int OFF_A0  = 33256;      // [4][64]  WeV0 @ Wo per head
constexpr int OFF_A1  = 33512;      // [4][64]
constexpr int OFF_K   = 33768;      // [64]     beV @ Wo + bo
constexpr int OFF_DUP = 33832;      // 10 x 64: g1lo,g1hi,lb1lo,lb1hi,b2lo,b2hi,g2lo,g2hi,lb2lo,lb2hi
constexpr int OFF_SCR = 34472;      // per-warp scratch
constexpr int SCR_FLOATS = 1568;    // x pairs [0,512) + h/pkb region [512,1568)
constexpr int SMEM_FLOATS = OFF_SCR + NWARPS * SCR_FLOATS;   // 51720 -> 206880 B

// ---- f32x2 helpers ----
__device__ __forceinline__ u64 pk2(float lo, float hi) {
    u64 r; asm("mov.b64 %0,{%1,%2};" : "=l"(r) : "f"(lo), "f"(hi)); return r;
}
__device__ __forceinline__ u64 dup2(float v) { return pk2(v, v); }
__device__ __forceinline__ void un2(u64 v, float& a, float& b) {
    asm("mov.b64 {%0,%1},%2;" : "=f"(a), "=f"(b) : "l"(v));
}
__device__ __forceinline__ u64 f2fma(u64 a, u64 b, u64 c) {
    u64 d; asm("fma.rn.f32x2 %0,%1,%2,%3;" : "=l"(d) : "l"(a), "l"(b), "l"(c)); return d;
}
__device__ __forceinline__ u64 f2add(u64 a, u64 b) {
    u64 d; asm("add.rn.f32x2 %0,%1,%2;" : "=l"(d) : "l"(a), "l"(b)); return d;
}
__device__ __forceinline__ u64 f2mul(u64 a, u64 b) {
    u64 d; asm("mul.rn.f32x2 %0,%1,%2;" : "=l"(d) : "l"(a), "l"(b)); return d;
}
__device__ __forceinline__ float ex2f(float x) {
    float y; asm("ex2.approx.f32 %0,%1;" : "=f"(y) : "f"(x)); return y;
}
__device__ __forceinline__ float bfly_add(float v) {
    #pragma unroll
    for (int o = 16; o >= 1; o >>= 1) v += __shfl_xor_sync(FULLMASK, v, o);
    return v;
}

// layernorm on row-pairs: vlo = channels L (rows p,p+4), vhi = channels L+32
__device__ __forceinline__ void ln_pair(u64 vlo, u64 vhi, u64 glo, u64 ghi, u64 blo, u64 bhi,
                                        u64& xlo, u64& xhi) {
    float sa, sb; un2(f2add(vlo, vhi), sa, sb);
    sa = bfly_add(sa); sb = bfly_add(sb);
    u64 mun = f2mul(pk2(sa, sb), dup2(-1.0f / 64.0f));
    u64 dlo = f2add(vlo, mun), dhi = f2add(vhi, mun);
    float qa, qb; un2(f2fma(dlo, dlo, f2mul(dhi, dhi)), qa, qb);
    qa = bfly_add(qa); qb = bfly_add(qb);
    float ra = rsqrtf(fmaf(qa, 1.0f / 64.0f, 1e-5f));
    float rb = rsqrtf(fmaf(qb, 1.0f / 64.0f, 1e-5f));
    u64 rs = pk2(ra, rb);
    xlo = f2fma(f2mul(dlo, rs), glo, blo);
    xhi = f2fma(f2mul(dhi, rs), ghi, bhi);
}

__global__ void __launch_bounds__(NTHREADS, 1)
main_kernel(const float* __restrict__ prec, const int* __restrict__ topmask,
            const float* __restrict__ We, const float* __restrict__ be,
            const float* __restrict__ Wq, const float* __restrict__ Wk,
            const float* __restrict__ Wv, const float* __restrict__ Wo,
            const float* __restrict__ bo,
            const float* __restrict__ g1, const float* __restrict__ lb1,
            const float* __restrict__ W1, const float* __restrict__ b1,
            const float* __restrict__ W2, const float* __restrict__ b2,
            const float* __restrict__ g2, const float* __restrict__ lb2,
            float* __restrict__ out)
{
    extern __shared__ float sm[];
    const int tid = threadIdx.x;

    // ---- stage big weights ----
    {
        float4* d = (float4*)(sm + OFF_W1);
        const float4* s = (const float4*)W1;
        for (int i = tid; i < 16384 / 4; i += NTHREADS) d[i] = s[i];
    }
    for (int i = tid; i < 256 * 32; i += NTHREADS) {   // W2 pairs
        int j = i >> 5, l = i & 31;
        sm[OFF_W2P + i * 2]     = W2[j * 64 + l];
        sm[OFF_W2P + i * 2 + 1] = W2[j * 64 + 32 + l];
    }
    if (tid < 256) sm[OFF_B1 + tid] = b1[tid];
    if (tid < 128) sm[OFF_WE + tid] = We[tid];
    if (tid >= 128 && tid < 192) sm[OFF_BE + tid - 128] = be[tid - 128];
    if (tid >= 192 && tid < 224) {
        int t = tid - 192;
        float v;
        v = g1[t];       sm[OFF_DUP + 0 * 64 + 2 * t] = v; sm[OFF_DUP + 0 * 64 + 2 * t + 1] = v;
        v = g1[32 + t];  sm[OFF_DUP + 1 * 64 + 2 * t] = v; sm[OFF_DUP + 1 * 64 + 2 * t + 1] = v;
        v = lb1[t];      sm[OFF_DUP + 2 * 64 + 2 * t] = v; sm[OFF_DUP + 2 * 64 + 2 * t + 1] = v;
        v = lb1[32 + t]; sm[OFF_DUP + 3 * 64 + 2 * t] = v; sm[OFF_DUP + 3 * 64 + 2 * t + 1] = v;
        v = b2[t];       sm[OFF_DUP + 4 * 64 + 2 * t] = v; sm[OFF_DUP + 4 * 64 + 2 * t + 1] = v;
        v = b2[32 + t];  sm[OFF_DUP + 5 * 64 + 2 * t] = v; sm[OFF_DUP + 5 * 64 + 2 * t + 1] = v;
        v = g2[t];       sm[OFF_DUP + 6 * 64 + 2 * t] = v; sm[OFF_DUP + 6 * 64 + 2 * t + 1] = v;
        v = g2[32 + t];  sm[OFF_DUP + 7 * 64 + 2 * t] = v; sm[OFF_DUP + 7 * 64 + 2 * t + 1] = v;
        v = lb2[t];      sm[OFF_DUP + 8 * 64 + 2 * t] = v; sm[OFF_DUP + 8 * 64 + 2 * t + 1] = v;
        v = lb2[32 + t]; sm[OFF_DUP + 9 * 64 + 2 * t] = v; sm[OFF_DUP + 9 * 64 + 2 * t + 1] = v;
    }

    // ---- setup stage 1: combined QKV embed weights (temps in warp0/1 scratch) ----
    float* tWQ = sm + OFF_SCR;
    float* tWK = tWQ + 128;
    float* tWV = tWK + 128;
    float* tbQ = tWV + 128;
    float* tbK = tbQ + 64;
    float* tbV = tbK + 64;
    if (tid < 64) {
        int j = tid, h = j >> 4, d = j & 15;
        float q0 = 0.f, q1 = 0.f, k0 = 0.f, k1 = 0.f, v0 = 0.f, v1 = 0.f;
        float bq = 0.f, bk = 0.f, bv = 0.f;
        for (int e = 0; e < 16; e++) {
            float we0 = We[h * 16 + e];
            float we1 = We[64 + h * 16 + e];
            float bb  = be[h * 16 + e];
            float wq = Wq[e * 16 + d], wk = Wk[e * 16 + d], wv = Wv[e * 16 + d];
            q0 = fmaf(we0, wq, q0); q1 = fmaf(we1, wq, q1); bq = fmaf(bb, wq, bq);
            k0 = fmaf(we0, wk, k0); k1 = fmaf(we1, wk, k1); bk = fmaf(bb, wk, bk);
            v0 = fmaf(we0, wv, v0); v1 = fmaf(we1, wv, v1); bv = fmaf(bb, wv, bv);
        }
        tWQ[j] = q0; tWQ[64 + j] = q1; tbQ[j] = bq;
        tWK[j] = k0; tWK[64 + j] = k1; tbK[j] = bk;
        tWV[j] = v0; tWV[64 + j] = v1; tbV[j] = bv;
    }
    __syncthreads();

    // ---- setup stage 2: bilinear energy forms + folded Wo ----
    if (tid < 4) {
        const float SC = 0.125f * 1.4426950408889634f;   // 1/sqrt(E) + log2e fold
        int hh = tid;
        float m00=0,m01=0,m02=0,m10=0,m11=0,m12=0,m20=0,m21=0,m22=0;
        for (int dd = 0; dd < 16; dd++) {
            float Q0 = tWQ[hh*16+dd], Q1 = tWQ[64+hh*16+dd], BQ = tbQ[hh*16+dd];
            float K0 = tWK[hh*16+dd], K1 = tWK[64+hh*16+dd], BK = tbK[hh*16+dd];
            m00 += Q0*K0; m01 += Q0*K1; m02 += Q0*BK;
            m10 += Q1*K0; m11 += Q1*K1; m12 += Q1*BK;
            m20 += BQ*K0; m21 += BQ*K1; m22 += BQ*BK;
        }
        sm[OFF_M+hh*9+0]=m00*SC; sm[OFF_M+hh*9+1]=m01*SC; sm[OFF_M+hh*9+2]=m02*SC;
        sm[OFF_M+hh*9+3]=m10*SC; sm[OFF_M+hh*9+4]=m11*SC; sm[OFF_M+hh*9+5]=m12*SC;
        sm[OFF_M+hh*9+6]=m20*SC; sm[OFF_M+hh*9+7]=m21*SC; sm[OFF_M+hh*9+8]=m22*SC;
    }
    if (tid >= 64 && tid < 128) {
        int j = tid - 64;
        float kk = 0.f;
        for (int hh = 0; hh < 4; hh++) {
            float s0 = 0.f, s1 = 0.f;
            for (int dd = 0; dd < 16; dd++) {
                int row = hh * 16 + dd;
                float w = Wo[row * 64 + j];
                s0 = fmaf(tWV[row], w, s0);
                s1 = fmaf(tWV[64 + row], w, s1);
                kk = fmaf(tbV[row], w, kk);
            }
            sm[OFF_A0 + hh * 64 + j] = s0;
            sm[OFF_A1 + hh * 64 + j] = s1;
        }
        sm[OFF_K + j] = kk + bo[j];
    }
    __syncthreads();

    const int warp = tid >> 5;
    const int L = tid & 31;
    float* scr = sm + OFF_SCR + warp * SCR_FLOATS;
    u64* sxp    = (u64*)scr;             // TRANSPOSED x: [64 channels][4 pairs] u64, floats [0,512)
    u64* shp    = (u64*)(scr + 512);     // [4][128] h chunk pairs, floats [512,1536)
    float4* pkb = (float4*)(scr + 512);  // [8][33]  (px, py, madd, 0), floats [512,1568) — aliases shp
    u64* uvb    = (u64*)scr;             // [32] (û, v̂) — aliases sxp head

    // hoisted per-lane constants
    const float we0l = sm[OFF_WE + L],      we1l = sm[OFF_WE + 64 + L],  bel = sm[OFF_BE + L];
    const float we0h = sm[OFF_WE + 32 + L], we1h = sm[OFF_WE + 96 + L], beh = sm[OFF_BE + 32 + L];
    u64 a0p[4], a1p[4];
    #pragma unroll
    for (int h = 0; h < 4; h++) {
        a0p[h] = pk2(sm[OFF_A0 + h * 64 + L], sm[OFF_A0 + h * 64 + 32 + L]);
        a1p[h] = pk2(sm[OFF_A1 + h * 64 + L], sm[OFF_A1 + h * 64 + 32 + L]);
    }
    const u64 kv2 = pk2(sm[OFF_K + L], sm[OFF_K + 32 + L]);
    const int rr = L >> 2, hh = L & 3;
    float Mh[9];
    #pragma unroll
    for (int i = 0; i < 9; i++) Mh[i] = sm[OFF_M + hh * 9 + i];

    const int g0 = warp * gridDim.x + blockIdx.x;
    const int gstride = gridDim.x * NWARPS;

    for (int g = g0; g < NGROUPS; g += gstride) {
        const int m0 = g * 8;
        const int bb = m0 / 192;             // 8 | 192: group stays in one batch row
        const int mk = topmask[bb * 32 + L];
        const float madd = (mk != 0) ? 0.0f : -4e18f;
        const int kqbase = m0 & 31;

        // ---- stage keys: (px, py, madd) per key, per row (stride-33, conflict-free) ----
        #pragma unroll
        for (int r = 0; r < 8; r++) {
            float2 p = ((const float2*)prec)[(m0 + r) * 32 + L];
            pkb[r * 33 + L] = make_float4(p.x, p.y, madd, 0.0f);
        }
        __syncwarp();

        // ---- transposed softmax: lane owns (row rr, head hh) ----
        {
            const float2 pq = *(const float2*)&pkb[rr * 33 + kqbase + rr];
            const float Ah = fmaf(pq.y, Mh[3], fmaf(pq.x, Mh[0], Mh[6]));
            const float Bh = fmaf(pq.y, Mh[4], fmaf(pq.x, Mh[1], Mh[7]));
            const float Ch = fmaf(pq.y, Mh[5], fmaf(pq.x, Mh[2], Mh[8]));
            float s = 0.f, u = 0.f, v = 0.f;
            const float4* row = &pkb[rr * 33];
            #pragma unroll 8
            for (int k = 0; k < 32; k++) {
                float4 t = row[k];
                float e = fmaf(Ah, t.x, fmaf(Bh, t.y, Ch)) + t.z;
                float p = ex2f(e);
                s += p;
                u = fmaf(p, t.x, u);
                v = fmaf(p, t.y, v);
            }
            const float inv = __fdividef(1.0f, s);
            __syncwarp();
            uvb[L] = pk2(u * inv, v * inv);
        }
        __syncwarp();

        // ---- qres + folded attention output ao (per row) ----
        float qres_l[8], qres_h[8];
        u64 ao[8];
        #pragma unroll
        for (int r = 0; r < 8; r++) {
            const float2 pq = *(const float2*)&pkb[r * 33 + kqbase + r];
            qres_l[r] = fmaf(pq.x, we0l, fmaf(pq.y, we1l, bel));
            qres_h[r] = fmaf(pq.x, we0h, fmaf(pq.y, we1h, beh));
            u64 a = kv2;
            #pragma unroll
            for (int h = 0; h < 4; h++) {
                const float2 uv = ((const float2*)uvb)[4 * r + h];
                a = f2fma(dup2(uv.x), a0p[h], f2fma(dup2(uv.y), a1p[h], a));
            }
            ao[r] = a;
        }
        __syncwarp();     // all uvb/pkb reads done before x / h stores overwrite those regions

        // ---- LN1 -> x pairs; store TRANSPOSED [channel][pair] via STS.128 ----
        u64 x_lo[4], x_hi[4];
        {
            const u64 g1l = *(const u64*)&sm[OFF_DUP + 0 * 64 + 2 * L];
            const u64 g1h = *(const u64*)&sm[OFF_DUP + 1 * 64 + 2 * L];
            const u64 l1l = *(const u64*)&sm[OFF_DUP + 2 * 64 + 2 * L];
            const u64 l1h = *(const u64*)&sm[OFF_DUP + 3 * 64 + 2 * L];
            #pragma unroll
            for (int p = 0; p < 4; p++) {
                float al, ah, bl, bhv;
                un2(ao[p], al, ah); un2(ao[p + 4], bl, bhv);
                u64 vlo = pk2(al + qres_l[p], bl + qres_l[p + 4]);
                u64 vhi = pk2(ah + qres_h[p], bhv + qres_h[p + 4]);
                ln_pair(vlo, vhi, g1l, g1h, l1l, l1h, x_lo[p], x_hi[p]);
            }
        }
        *(ulonglong2*)&sxp[L * 4]            = make_ulonglong2(x_lo[0], x_lo[1]);
        *(ulonglong2*)&sxp[L * 4 + 2]        = make_ulonglong2(x_lo[2], x_lo[3]);
        *(ulonglong2*)&sxp[(32 + L) * 4]     = make_ulonglong2(x_hi[0], x_hi[1]);
        *(ulonglong2*)&sxp[(32 + L) * 4 + 2] = make_ulonglong2(x_hi[2], x_hi[3]);
        __syncwarp();

        // ---- Phase C: h = relu(x @ W1 + b1), all 8 owned channels in one pass ----
        u64 hacc[4][8];
        {
            const float4 b1a = *(const float4*)&sm[OFF_B1 + 4 * L];
            const float4 b1b = *(const float4*)&sm[OFF_B1 + 128 + 4 * L];
            const u64 i0 = dup2(b1a.x), i1 = dup2(b1a.y), i2 = dup2(b1a.z), i3 = dup2(b1a.w);
            const u64 i4 = dup2(b1b.x), i5 = dup2(b1b.y), i6 = dup2(b1b.z), i7 = dup2(b1b.w);
            #pragma unroll
            for (int p = 0; p < 4; p++) {
                hacc[p][0]=i0; hacc[p][1]=i1; hacc[p][2]=i2; hacc[p][3]=i3;
                hacc[p][4]=i4; hacc[p][5]=i5; hacc[p][6]=i6; hacc[p][7]=i7;
            }
        }
        #pragma unroll 4
        for (int j = 0; j < 64; j++) {
            const float4 wa = *(const float4*)&sm[OFF_W1 + j * 256 + 4 * L];
            const float4 wb = *(const float4*)&sm[OFF_W1 + j * 256 + 128 + 4 * L];
            const u64 w0 = dup2(wa.x), w1 = dup2(wa.y), w2 = dup2(wa.z), w3 = dup2(wa.w);
            const u64 w4 = dup2(wb.x), w5 = dup2(wb.y), w6 = dup2(wb.z), w7 = dup2(wb.w);
            const ulonglong2 xq0 = *(const ulonglong2*)&sxp[j * 4];      // pairs 0,1 (broadcast)
            const ulonglong2 xq1 = *(const ulonglong2*)&sxp[j * 4 + 2];  // pairs 2,3
            const u64 xj[4] = { xq0.x, xq0.y, xq1.x, xq1.y };
            #pragma unroll
            for (int p = 0; p < 4; p++) {
                hacc[p][0] = f2fma(xj[p], w0, hacc[p][0]);
                hacc[p][1] = f2fma(xj[p], w1, hacc[p][1]);
                hacc[p][2] = f2fma(xj[p], w2, hacc[p][2]);
                hacc[p][3] = f2fma(xj[p], w3, hacc[p][3]);
                hacc[p][4] = f2fma(xj[p], w4, hacc[p][4]);
                hacc[p][5] = f2fma(xj[p], w5, hacc[p][5]);
                hacc[p][6] = f2fma(xj[p], w6, hacc[p][6]);
                hacc[p][7] = f2fma(xj[p], w7, hacc[p][7]);
            }
        }

        // ---- Phase D: y = h @ W2 + b2, chunked, W2 pre-paired, STS.128 h stores ----
        u64 y_lo[4], y_hi[4];
        {
            const u64 b2l = *(const u64*)&sm[OFF_DUP + 4 * 64 + 2 * L];
            const u64 b2h = *(const u64*)&sm[OFF_DUP + 5 * 64 + 2 * L];
            #pragma unroll
            for (int p = 0; p < 4; p++) { y_lo[p] = b2l; y_hi[p] = b2h; }
        }
        #pragma unroll 1
        for (int cc = 0; cc < 2; cc++) {
            // relu + store this chunk (hacc[.][cc*4 + t] = channels cc*128 + 4L + t)
            #pragma unroll
            for (int p = 0; p < 4; p++) {
                u64 hr[4];
                #pragma unroll
                for (int t = 0; t < 4; t++) {
                    float a, b; un2(hacc[p][cc * 4 + t], a, b);
                    hr[t] = pk2(fmaxf(a, 0.0f), fmaxf(b, 0.0f));
                }
                *(ulonglong2*)&shp[p * 128 + 4 * L]     = make_ulonglong2(hr[0], hr[1]);
                *(ulonglong2*)&shp[p * 128 + 4 * L + 2] = make_ulonglong2(hr[2], hr[3]);
            }
            __syncwarp();
            const float* W2c = sm + OFF_W2P + cc * 128 * 64;   // float2[128][32] region
            #pragma unroll 4
            for (int u = 0; u < 64; u++) {
                const int jj = 2 * u;
                const u64 wa = *(const u64*)&W2c[jj * 64 + 2 * L];        // (W2[j][L], W2[j][L+32])
                const u64 wb = *(const u64*)&W2c[(jj + 1) * 64 + 2 * L];
                float wal, wah, wbl, wbh; un2(wa, wal, wah); un2(wb, wbl, wbh);
                const u64 wal2 = dup2(wal), wah2 = dup2(wah), wbl2 = dup2(wbl), wbh2 = dup2(wbh);
                #pragma unroll
                for (int p = 0; p < 4; p++) {
                    ulonglong2 h2v = *(const ulonglong2*)&shp[p * 128 + jj];  // LDS.128 broadcast
                    y_lo[p] = f2fma(h2v.x, wal2, y_lo[p]);
                    y_hi[p] = f2fma(h2v.x, wah2, y_hi[p]);
                    y_lo[p] = f2fma(h2v.y, wbl2, y_lo[p]);
                    y_hi[p] = f2fma(h2v.y, wbh2, y_hi[p]);
                }
            }
            __syncwarp();
        }

        // ---- LN2 + store ----
        {
            const u64 g2l = *(const u64*)&sm[OFF_DUP + 6 * 64 + 2 * L];
            const u64 g2h = *(const u64*)&sm[OFF_DUP + 7 * 64 + 2 * L];
            const u64 l2l = *(const u64*)&sm[OFF_DUP + 8 * 64 + 2 * L];
            const u64 l2h = *(const u64*)&sm[OFF_DUP + 9 * 64 + 2 * L];
            #pragma unroll
            for (int p = 0; p < 4; p++) {
                u64 vlo = f2add(y_lo[p], x_lo[p]);
                u64 vhi = f2add(y_hi[p], x_hi[p]);
                u64 olo, ohi;
                ln_pair(vlo, vhi, g2l, g2h, l2l, l2h, olo, ohi);
                float a, b, c, d;
                un2(olo, a, b); un2(ohi, c, d);
                out[(m0 + p) * 64 + L]           = a;
                out[(m0 + p + 4) * 64 + L]       = b;
                out[(m0 + p) * 64 + 32 + L]      = c;
                out[(m0 + p + 4) * 64 + 32 + L]  = d;
            }
        }
        __syncwarp();   // shp/sxp reads done before next group's pkb stores
    }
}

extern "C" void kernel_launch(void* const* d_in, const int* in_sizes, int n_in,
                              void* d_out, int out_size) {
    const float* prec = (const float*)d_in[0];
    const int*   msk  = (const int*)d_in[1];
    const float* We   = (const float*)d_in[2];
    const float* be   = (const float*)d_in[3];
    const float* Wq   = (const float*)d_in[4];
    const float* Wk   = (const float*)d_in[5];
    const float* Wv   = (const float*)d_in[6];
    const float* Wo   = (const float*)d_in[7];
    const float* bo   = (const float*)d_in[8];
    const float* g1   = (const float*)d_in[9];
    const float* lb1  = (const float*)d_in[10];
    const float* W1   = (const float*)d_in[11];
    const float* b1   = (const float*)d_in[12];
    const float* W2   = (const float*)d_in[13];
    const float* b2   = (const float*)d_in[14];
    const float* g2   = (const float*)d_in[15];
    const float* lb2  = (const float*)d_in[16];
    float* out = (float*)d_out;

    const int smem_bytes = SMEM_FLOATS * (int)sizeof(float);
    cudaFuncSetAttribute(main_kernel, cudaFuncAttributeMaxDynamicSharedMemorySize, smem_bytes);

    int nsm = 148;
    cudaDeviceGetAttribute(&nsm, cudaDevAttrMultiProcessorCount, 0);

    main_kernel<<<nsm, NTHREADS, smem_bytes>>>(prec, msk, We, be, Wq, Wk, Wv, Wo, bo,
                                               g1, lb1, W1, b1, W2, b2, g2, lb2, out);
}